// round 12
// baseline (speedup 1.0000x reference)
#include <cuda_runtime.h>
#include <math.h>
#include <stdint.h>

// Problem constants
#define Bb   4
#define Ss   1024
#define Dd   1024
#define Hh   16
#define DKk  64
#define Rr   257          // 2*MAX_REL + 1
#define BHh  64           // B*H
#define Mm   4096         // B*S
#define BHS  65536        // B*H*S
#define SCALEF 0.125f     // 1/sqrt(64)
#define KC   32           // k-chunk
#define PKC  16           // packed k-chunk (bf16 pairs)
#define PKP  20           // padded packed stride (80B rows: 16B-aligned for ldmatrix, conflict-free)
#define PKP2 17           // scalar-load stride (fctx B)

// ---------------- scratch (device globals; no runtime allocation) ----------------
__device__ float g_Q[BHS * DKk];
__device__ float g_K[BHS * DKk];
__device__ float g_V[BHS * DKk];
__device__ float g_ctx[BHS * DKk];
__device__ float g_Qrel[BHS * Rr];
__device__ float g_arel[BHS * Rr];
__device__ float g_attn[67108864];        // [B,H,S,S] scores
__device__ float2 g_part[BHS * 8];        // per-(row, r-tile) softmax partials

// ---------------- split-bf16 helpers ----------------
__device__ __forceinline__ void split2(float x0, float x1, uint32_t& h, uint32_t& l) {
    uint32_t hp;
    asm("cvt.rn.bf16x2.f32 %0, %1, %2;" : "=r"(hp) : "f"(x1), "f"(x0));
    float h0 = __uint_as_float(hp << 16);
    float h1 = __uint_as_float(hp & 0xffff0000u);
    float r0 = x0 - h0, r1 = x1 - h1;
    uint32_t lp;
    asm("cvt.rn.bf16x2.f32 %0, %1, %2;" : "=r"(lp) : "f"(r1), "f"(r0));
    h = hp; l = lp;
}
__device__ __forceinline__ void mma_bf16(float* c, const uint32_t* a, const uint32_t* b) {
    asm volatile(
        "mma.sync.aligned.m16n8k16.row.col.f32.bf16.bf16.f32 "
        "{%0,%1,%2,%3}, {%4,%5,%6,%7}, {%8,%9}, {%0,%1,%2,%3};\n"
        : "+f"(c[0]), "+f"(c[1]), "+f"(c[2]), "+f"(c[3])
        : "r"(a[0]), "r"(a[1]), "r"(a[2]), "r"(a[3]), "r"(b[0]), "r"(b[1]));
}
__device__ __forceinline__ void ldsm_x4(uint32_t& r0, uint32_t& r1, uint32_t& r2,
                                        uint32_t& r3, uint32_t addr) {
    asm volatile("ldmatrix.sync.aligned.m8n8.x4.shared.b16 {%0,%1,%2,%3}, [%4];"
                 : "=r"(r0), "=r"(r1), "=r"(r2), "=r"(r3) : "r"(addr));
}
__device__ __forceinline__ void cpa16(void* dst, const void* src) {
    uint32_t s = (uint32_t)__cvta_generic_to_shared(dst);
    asm volatile("cp.async.ca.shared.global [%0], [%1], 16;" :: "r"(s), "l"(src));
}
#define CP_WAIT() do { asm volatile("cp.async.commit_group;\ncp.async.wait_group 0;" ::: "memory"); } while (0)

// ldmatrix-fed split-bf16 chunk (A + B via LDSM; both [row][pk], stride PKP).
// Requires locals: warp_m, warp_n, lq, ls1, ls2, uAh, uAl, uBsel, c[][][]
// Lane mapping: lanes 0-7 -> tile0, 8-15 -> tile1(+8 rows / +4 cols), 16-23 -> tile2, 24-31 -> tile3.
#define MMA_CHUNK_LDSM()                                                         \
    _Pragma("unroll")                                                            \
    for (int ks2 = 0; ks2 < PKC; ks2 += 8) {                                     \
        uint32_t ah[4][4], al[4][4], bh[4][2], bl[4][2];                         \
        _Pragma("unroll")                                                        \
        for (int mt = 0; mt < 4; mt++) {                                         \
            uint32_t ra = (uint32_t)(((warp_m * 64 + mt * 16 + lq + ls1 * 8) * PKP \
                                      + ks2 + ls2 * 4) * 4);                     \
            ldsm_x4(ah[mt][0], ah[mt][1], ah[mt][2], ah[mt][3], uAh + ra);       \
            ldsm_x4(al[mt][0], al[mt][1], al[mt][2], al[mt][3], uAl + ra);       \
        }                                                                        \
        _Pragma("unroll")                                                        \
        for (int nt = 0; nt < 4; nt++) {                                         \
            uint32_t rb = (uint32_t)(((warp_n * 32 + nt * 8 + lq) * PKP          \
                                      + ks2 + ls1 * 4) * 4);                     \
            ldsm_x4(bh[nt][0], bh[nt][1], bl[nt][0], bl[nt][1], uBsel + rb);     \
        }                                                                        \
        _Pragma("unroll")                                                        \
        for (int mt = 0; mt < 4; mt++)                                           \
            _Pragma("unroll")                                                    \
            for (int nt = 0; nt < 4; nt++) {                                     \
                mma_bf16(c[mt][nt], ah[mt], bh[nt]);                             \
                mma_bf16(c[mt][nt], ah[mt], bl[nt]);                             \
                mma_bf16(c[mt][nt], al[mt], bh[nt]);                             \
            }                                                                    \
    }

// fctx variant: A via LDSM (stride PKP), B scalar from [k-packed? no: [n][pk]] stride PKP2
#define MMA_CHUNK_LDSM_A(BH_, BL_)                                               \
    _Pragma("unroll")                                                            \
    for (int ks2 = 0; ks2 < PKC; ks2 += 8) {                                     \
        uint32_t ah[4][4], al[4][4], bh[4][2], bl[4][2];                         \
        _Pragma("unroll")                                                        \
        for (int mt = 0; mt < 4; mt++) {                                         \
            uint32_t ra = (uint32_t)(((warp_m * 64 + mt * 16 + lq + ls1 * 8) * PKP \
                                      + ks2 + ls2 * 4) * 4);                     \
            ldsm_x4(ah[mt][0], ah[mt][1], ah[mt][2], ah[mt][3], uAh + ra);       \
            ldsm_x4(al[mt][0], al[mt][1], al[mt][2], al[mt][3], uAl + ra);       \
        }                                                                        \
        _Pragma("unroll")                                                        \
        for (int nt = 0; nt < 4; nt++) {                                         \
            int col = warp_n * 32 + nt * 8;                                      \
            bh[nt][0] = BH_[col + g][ks2 + tg];                                  \
            bh[nt][1] = BH_[col + g][ks2 + 4 + tg];                              \
            bl[nt][0] = BL_[col + g][ks2 + tg];                                  \
            bl[nt][1] = BL_[col + g][ks2 + 4 + tg];                              \
        }                                                                        \
        _Pragma("unroll")                                                        \
        for (int mt = 0; mt < 4; mt++)                                           \
            _Pragma("unroll")                                                    \
            for (int nt = 0; nt < 4; nt++) {                                     \
                mma_bf16(c[mt][nt], ah[mt], bh[nt]);                             \
                mma_bf16(c[mt][nt], ah[mt], bl[nt]);                             \
                mma_bf16(c[mt][nt], al[mt], bh[nt]);                             \
            }                                                                    \
    }

// =================================================================================
// Kernel 1: QKV projection. grid (8, 32), 256 threads (2m x 4n warps)
// =================================================================================
__global__ __launch_bounds__(256) void proj_mma(const float* __restrict__ X,
                                                const float* __restrict__ W,
                                                const float* __restrict__ bias,
                                                float* __restrict__ out)
{
    __shared__ uint32_t Ahp[128][PKP], Alp[128][PKP];
    __shared__ uint32_t Bhp[128][PKP], Blp[128][PKP];
    int n0 = blockIdx.x * 128, m0 = blockIdx.y * 128;
    int tid = threadIdx.x, warp = tid >> 5, lane = tid & 31;
    int warp_m = warp >> 2, warp_n = warp & 3;
    int g = lane >> 2, tg = lane & 3;
    (void)g; (void)tg;
    int lq = lane & 7, ls1 = (lane >> 3) & 1, ls2 = lane >> 4;
    uint32_t uAh = (uint32_t)__cvta_generic_to_shared(Ahp);
    uint32_t uAl = (uint32_t)__cvta_generic_to_shared(Alp);
    uint32_t uBh = (uint32_t)__cvta_generic_to_shared(Bhp);
    uint32_t uBl = (uint32_t)__cvta_generic_to_shared(Blp);
    uint32_t uBsel = (lane < 16) ? uBh : uBl;
    float c[4][4][4] = {};

    for (int k0 = 0; k0 < Dd; k0 += KC) {
        for (int i = tid; i < 2048; i += 256) {
            int r = i >> 4, pc = i & 15;
            float2 a = *(const float2*)&X[(size_t)(m0 + r) * Dd + k0 + 2 * pc];
            split2(a.x, a.y, Ahp[r][pc], Alp[r][pc]);
            float2 b = *(const float2*)&W[(size_t)(n0 + r) * Dd + k0 + 2 * pc];
            split2(b.x, b.y, Bhp[r][pc], Blp[r][pc]);
        }
        __syncthreads();
        MMA_CHUNK_LDSM()
        __syncthreads();
    }
    #pragma unroll
    for (int mt = 0; mt < 4; mt++)
        #pragma unroll
        for (int rr = 0; rr < 2; rr++) {
            int m = m0 + warp_m * 64 + mt * 16 + (lane >> 2) + rr * 8;
            int b = m >> 10, s = m & 1023;
            #pragma unroll
            for (int nt = 0; nt < 4; nt++) {
                int n = n0 + warp_n * 32 + nt * 8 + (lane & 3) * 2;
                float v0 = c[mt][nt][rr * 2 + 0] + bias[n];
                float v1 = c[mt][nt][rr * 2 + 1] + bias[n + 1];
                out[((b * Hh + (n >> 6)) * Ss + s) * DKk + (n & 63)] = v0;
                int n1 = n + 1;
                out[((b * Hh + (n1 >> 6)) * Ss + s) * DKk + (n1 & 63)] = v1;
            }
        }
}

// =================================================================================
// Kernel 2: Qrel. grid (3, 512)
// =================================================================================
__global__ __launch_bounds__(256) void qrel_mma(const float* __restrict__ relk)
{
    __shared__ uint32_t Ahp[128][PKP], Alp[128][PKP];
    __shared__ uint32_t Bhp[128][PKP], Blp[128][PKP];
    int n0 = blockIdx.x * 128, m0 = blockIdx.y * 128;
    int tid = threadIdx.x, warp = tid >> 5, lane = tid & 31;
    int warp_m = warp >> 2, warp_n = warp & 3;
    int lq = lane & 7, ls1 = (lane >> 3) & 1, ls2 = lane >> 4;
    uint32_t uAh = (uint32_t)__cvta_generic_to_shared(Ahp);
    uint32_t uAl = (uint32_t)__cvta_generic_to_shared(Alp);
    uint32_t uBh = (uint32_t)__cvta_generic_to_shared(Bhp);
    uint32_t uBl = (uint32_t)__cvta_generic_to_shared(Blp);
    uint32_t uBsel = (lane < 16) ? uBh : uBl;
    float c[4][4][4] = {};

    for (int k0 = 0; k0 < DKk; k0 += KC) {
        for (int i = tid; i < 2048; i += 256) {
            int r = i >> 4, pc = i & 15;
            float2 a = *(const float2*)&g_Q[(size_t)(m0 + r) * DKk + k0 + 2 * pc];
            split2(a.x, a.y, Ahp[r][pc], Alp[r][pc]);
            float2 b = make_float2(0.f, 0.f);
            if (n0 + r < Rr) b = *(const float2*)&relk[(size_t)(n0 + r) * DKk + k0 + 2 * pc];
            split2(b.x, b.y, Bhp[r][pc], Blp[r][pc]);
        }
        __syncthreads();
        MMA_CHUNK_LDSM()
        __syncthreads();
    }
    #pragma unroll
    for (int mt = 0; mt < 4; mt++)
        #pragma unroll
        for (int rr = 0; rr < 2; rr++) {
            int m = m0 + warp_m * 64 + mt * 16 + (lane >> 2) + rr * 8;
            #pragma unroll
            for (int nt = 0; nt < 4; nt++) {
                int n = n0 + warp_n * 32 + nt * 8 + (lane & 3) * 2;
                if (n < Rr)     g_Qrel[(size_t)m * Rr + n]     = c[mt][nt][rr * 2 + 0];
                if (n + 1 < Rr) g_Qrel[(size_t)m * Rr + n + 1] = c[mt][nt][rr * 2 + 1];
            }
        }
}

// =================================================================================
// Kernel 3: scores + rel-K gather + mask -> g_attn + softmax partials -> g_part
// grid (8, 8, 64), 256 threads
// =================================================================================
__global__ __launch_bounds__(256) void scores_mma(const int* __restrict__ mask)
{
    __shared__ uint32_t Ahp[128][PKP], Alp[128][PKP];
    __shared__ uint32_t Bhp[128][PKP], Blp[128][PKP];
    __shared__ float redm[4][128];
    __shared__ float reds[4][128];
    __shared__ int msk[128];
    int z = blockIdx.z;
    int r0 = blockIdx.x * 128, l0 = blockIdx.y * 128;
    const float* Qb = g_Q + (size_t)z * Ss * DKk;
    const float* Kb = g_K + (size_t)z * Ss * DKk;
    int tid = threadIdx.x, warp = tid >> 5, lane = tid & 31;
    int warp_m = warp >> 2, warp_n = warp & 3;
    int g = lane >> 2, tg = lane & 3;
    int lq = lane & 7, ls1 = (lane >> 3) & 1, ls2 = lane >> 4;
    uint32_t uAh = (uint32_t)__cvta_generic_to_shared(Ahp);
    uint32_t uAl = (uint32_t)__cvta_generic_to_shared(Alp);
    uint32_t uBh = (uint32_t)__cvta_generic_to_shared(Bhp);
    uint32_t uBl = (uint32_t)__cvta_generic_to_shared(Blp);
    uint32_t uBsel = (lane < 16) ? uBh : uBl;
    float c[4][4][4] = {};

    if (tid < 128) msk[tid] = mask[(z >> 4) * Ss + r0 + tid];

    for (int k0 = 0; k0 < DKk; k0 += KC) {
        for (int i = tid; i < 2048; i += 256) {
            int r = i >> 4, pc = i & 15;
            float2 a = *(const float2*)&Qb[(size_t)(l0 + r) * DKk + k0 + 2 * pc];
            split2(a.x, a.y, Ahp[r][pc], Alp[r][pc]);
            float2 b = *(const float2*)&Kb[(size_t)(r0 + r) * DKk + k0 + 2 * pc];
            split2(b.x, b.y, Bhp[r][pc], Blp[r][pc]);
        }
        __syncthreads();
        MMA_CHUNK_LDSM()
        __syncthreads();
    }
    // epilogue: finalize scores in-place, write to g_attn, per-row tile max
    #pragma unroll
    for (int mt = 0; mt < 4; mt++)
        #pragma unroll
        for (int rr = 0; rr < 2; rr++) {
            int row_local = warp_m * 64 + mt * 16 + rr * 8 + g;
            int l = l0 + row_local;
            const float* qr = &g_Qrel[(size_t)(z * Ss + l) * Rr];
            float* arow = &g_attn[(size_t)(z * Ss + l) * Ss];
            float vmax = -INFINITY;
            #pragma unroll
            for (int nt = 0; nt < 4; nt++) {
                int r = r0 + warp_n * 32 + nt * 8 + tg * 2;
                #pragma unroll
                for (int e = 0; e < 2; e++) {
                    int rc = r + e;
                    float sc = c[mt][nt][rr * 2 + e] * SCALEF;
                    int rel = rc - l;
                    rel = rel < -128 ? -128 : (rel > 128 ? 128 : rel);
                    sc += qr[rel + 128];
                    if (msk[rc - r0] == 0) sc = -1000000000.0f;
                    c[mt][nt][rr * 2 + e] = sc;
                    arow[rc] = sc;
                    vmax = fmaxf(vmax, sc);
                }
            }
            vmax = fmaxf(vmax, __shfl_xor_sync(0xffffffffu, vmax, 1));
            vmax = fmaxf(vmax, __shfl_xor_sync(0xffffffffu, vmax, 2));
            if (tg == 0) redm[warp_n][row_local] = vmax;
        }
    __syncthreads();
    #pragma unroll
    for (int mt = 0; mt < 4; mt++)
        #pragma unroll
        for (int rr = 0; rr < 2; rr++) {
            int row_local = warp_m * 64 + mt * 16 + rr * 8 + g;
            float tmax = fmaxf(fmaxf(redm[0][row_local], redm[1][row_local]),
                               fmaxf(redm[2][row_local], redm[3][row_local]));
            float s = 0.f;
            #pragma unroll
            for (int nt = 0; nt < 4; nt++)
                #pragma unroll
                for (int e = 0; e < 2; e++)
                    s += expf(c[mt][nt][rr * 2 + e] - tmax);
            s += __shfl_xor_sync(0xffffffffu, s, 1);
            s += __shfl_xor_sync(0xffffffffu, s, 2);
            if (tg == 0) reds[warp_n][row_local] = s;
        }
    __syncthreads();
    if (tid < 128) {
        float tm = fmaxf(fmaxf(redm[0][tid], redm[1][tid]),
                         fmaxf(redm[2][tid], redm[3][tid]));
        float Zt = reds[0][tid] + reds[1][tid] + reds[2][tid] + reds[3][tid];
        g_part[((size_t)z * Ss + l0 + tid) * 8 + blockIdx.x] = make_float2(tm, Zt);
    }
}

// =================================================================================
// Kernel 4 (fused softmax + context). grid (8, 64), 128 threads (thread == l-row)
// A via ldmatrix (stride PKP); B scalar (stride PKP2) to fit 48KB smem.
// =================================================================================
__global__ __launch_bounds__(128) void fctx_mma(const float* __restrict__ relv)
{
    __shared__ float Sf[128][36];              // fp32 score staging (144B rows: 16B-aligned)
    __shared__ uint32_t Ahp[128][PKP], Alp[128][PKP];
    __shared__ uint32_t Bhp[64][PKP2], Blp[64][PKP2];
    int z = blockIdx.y;
    int l0 = blockIdx.x * 128;
    int tid = threadIdx.x, warp = tid >> 5, lane = tid & 31;
    int warp_m = warp >> 1, warp_n = warp & 1;
    int g = lane >> 2, tg = lane & 3;
    int lq = lane & 7, ls1 = (lane >> 3) & 1, ls2 = lane >> 4;
    uint32_t uAh = (uint32_t)__cvta_generic_to_shared(Ahp);
    uint32_t uAl = (uint32_t)__cvta_generic_to_shared(Alp);
    const float* Vb = g_V + (size_t)z * Ss * DKk;
    float c[4][4][4] = {};

    // --- per-row softmax stats (thread tid owns row l0+tid) ---
    int l = l0 + tid;
    float m = -INFINITY, Z = 0.f;
    {
        const float2* pp = &g_part[((size_t)z * Ss + l) * 8];
        float2 v[8];
        #pragma unroll
        for (int i = 0; i < 8; i++) { v[i] = pp[i]; m = fmaxf(m, v[i].x); }
        #pragma unroll
        for (int i = 0; i < 8; i++) Z += v[i].y * expf(v[i].x - m);
    }
    float invZ = 1.f / Z;
    float* arow = &g_arel[(size_t)(z * Ss + l) * Rr];
    for (int p = 1; p <= 127 - l; p++) arow[p] = 0.f;
    for (int p = 1152 - l; p <= 255; p++) arow[p] = 0.f;
    float p0a = 0.f, p256a = 0.f;

    // --- streaming pass: scores tile -> probs (packed bf16) -> arel + PV MMA ---
    for (int r0 = 0; r0 < Ss; r0 += KC) {
        for (int i = tid; i < 1024; i += 128) {          // scores: 128 rows x 8 float4
            int r = i >> 3, c4 = (i & 7) * 4;
            cpa16(&Sf[r][c4], &g_attn[(size_t)(z * Ss + l0 + r) * Ss + r0 + c4]);
        }
        for (int i = tid; i < 1024; i += 128) {          // V^T: 64 d x 16 pk
            int d = i & 63, pk = i >> 6;
            float v0 = Vb[(size_t)(r0 + 2 * pk) * DKk + d];
            float v1 = Vb[(size_t)(r0 + 2 * pk + 1) * DKk + d];
            split2(v0, v1, Bhp[d][pk], Blp[d][pk]);
        }
        CP_WAIT();
        __syncthreads();
        // transform own row: scores -> probs, bucket arel, pack to bf16
        #pragma unroll
        for (int pc = 0; pc < PKC; pc++) {
            float s0 = Sf[tid][2 * pc], s1 = Sf[tid][2 * pc + 1];
            float p0f = expf(s0 - m) * invZ;
            float p1f = expf(s1 - m) * invZ;
            int rel0 = r0 + 2 * pc - l;
            if (rel0 <= -128) p0a += p0f;
            else if (rel0 >= 128) p256a += p0f;
            else arow[rel0 + 128] = p0f;
            int rel1 = rel0 + 1;
            if (rel1 <= -128) p0a += p1f;
            else if (rel1 >= 128) p256a += p1f;
            else arow[rel1 + 128] = p1f;
            split2(p0f, p1f, Ahp[tid][pc], Alp[tid][pc]);
        }
        __syncthreads();
        MMA_CHUNK_LDSM_A(Bhp, Blp)
        __syncthreads();
    }
    arow[0] = p0a;
    arow[256] = p256a;
    __syncthreads();

    // --- rel-value part: K = 257 in zero-padded chunks ---
    for (int p0 = 0; p0 < Rr; p0 += KC) {
        for (int i = tid; i < 2048; i += 128) {
            int r = i >> 4, pc = i & 15;
            int p = p0 + 2 * pc;
            float a0 = (p     < Rr) ? g_arel[(size_t)(z * Ss + l0 + r) * Rr + p]     : 0.f;
            float a1 = (p + 1 < Rr) ? g_arel[(size_t)(z * Ss + l0 + r) * Rr + p + 1] : 0.f;
            split2(a0, a1, Ahp[r][pc], Alp[r][pc]);
        }
        for (int i = tid; i < 1024; i += 128) {
            int d = i & 63, pk = i >> 6;
            int p = p0 + 2 * pk;
            float v0 = (p     < Rr) ? relv[(size_t)p * DKk + d]       : 0.f;
            float v1 = (p + 1 < Rr) ? relv[(size_t)(p + 1) * DKk + d] : 0.f;
            split2(v0, v1, Bhp[d][pk], Blp[d][pk]);
        }
        __syncthreads();
        MMA_CHUNK_LDSM_A(Bhp, Blp)
        __syncthreads();
    }
    #pragma unroll
    for (int mt = 0; mt < 4; mt++)
        #pragma unroll
        for (int rr = 0; rr < 2; rr++) {
            int lr = l0 + warp_m * 64 + mt * 16 + g + rr * 8;
            #pragma unroll
            for (int nt = 0; nt < 4; nt++) {
                int d = warp_n * 32 + nt * 8 + tg * 2;
                g_ctx[(size_t)(z * Ss + lr) * DKk + d]     = c[mt][nt][rr * 2 + 0];
                g_ctx[(size_t)(z * Ss + lr) * DKk + d + 1] = c[mt][nt][rr * 2 + 1];
            }
        }
}

// =================================================================================
// Kernel 5: outproj. grid (8, 32), 256 threads
// =================================================================================
__global__ __launch_bounds__(256) void outproj_mma(const float* __restrict__ Wo,
                                                   const float* __restrict__ bo,
                                                   float* __restrict__ out)
{
    __shared__ uint32_t Ahp[128][PKP], Alp[128][PKP];
    __shared__ uint32_t Bhp[128][PKP], Blp[128][PKP];
    int n0 = blockIdx.x * 128, m0 = blockIdx.y * 128;
    int tid = threadIdx.x, warp = tid >> 5, lane = tid & 31;
    int warp_m = warp >> 2, warp_n = warp & 3;
    int lq = lane & 7, ls1 = (lane >> 3) & 1, ls2 = lane >> 4;
    uint32_t uAh = (uint32_t)__cvta_generic_to_shared(Ahp);
    uint32_t uAl = (uint32_t)__cvta_generic_to_shared(Alp);
    uint32_t uBh = (uint32_t)__cvta_generic_to_shared(Bhp);
    uint32_t uBl = (uint32_t)__cvta_generic_to_shared(Blp);
    uint32_t uBsel = (lane < 16) ? uBh : uBl;
    float c[4][4][4] = {};

    for (int k0 = 0; k0 < Dd; k0 += KC) {
        int h = k0 >> 6, dk0 = k0 & 63;
        for (int i = tid; i < 2048; i += 256) {
            int r = i >> 4, pc = i & 15;
            int mm = m0 + r, b = mm >> 10, s = mm & 1023;
            float2 a = *(const float2*)&g_ctx[(size_t)((b * Hh + h) * Ss + s) * DKk + dk0 + 2 * pc];
            split2(a.x, a.y, Ahp[r][pc], Alp[r][pc]);
            float2 w = *(const float2*)&Wo[(size_t)(n0 + r) * Dd + k0 + 2 * pc];
            split2(w.x, w.y, Bhp[r][pc], Blp[r][pc]);
        }
        __syncthreads();
        MMA_CHUNK_LDSM()
        __syncthreads();
    }
    #pragma unroll
    for (int mt = 0; mt < 4; mt++)
        #pragma unroll
        for (int rr = 0; rr < 2; rr++) {
            int mm = m0 + warp_m * 64 + mt * 16 + (lane >> 2) + rr * 8;
            #pragma unroll
            for (int nt = 0; nt < 4; nt++) {
                int n = n0 + warp_n * 32 + nt * 8 + (lane & 3) * 2;
                out[(size_t)mm * Dd + n]     = c[mt][nt][rr * 2 + 0] + bo[n];
                out[(size_t)mm * Dd + n + 1] = c[mt][nt][rr * 2 + 1] + bo[n + 1];
            }
        }
}

extern "C" void kernel_launch(void* const* d_in, const int* in_sizes, int n_in,
                              void* d_out, int out_size)
{
    const float* query = (const float*)d_in[0];
    const float* key   = (const float*)d_in[1];
    const float* value = (const float*)d_in[2];
    const int*   mask  = (const int*)  d_in[3];
    const float* w_q   = (const float*)d_in[4];
    const float* b_q   = (const float*)d_in[5];
    const float* w_k   = (const float*)d_in[6];
    const float* b_k   = (const float*)d_in[7];
    const float* w_v   = (const float*)d_in[8];
    const float* b_v   = (const float*)d_in[9];
    const float* w_o   = (const float*)d_in[10];
    const float* b_o   = (const float*)d_in[11];
    const float* rel_k = (const float*)d_in[12];
    const float* rel_v = (const float*)d_in[13];
    float* out = (float*)d_out;

    float *pQ, *pK, *pV;
    cudaGetSymbolAddress((void**)&pQ, g_Q);
    cudaGetSymbolAddress((void**)&pK, g_K);
    cudaGetSymbolAddress((void**)&pV, g_V);

    dim3 gProj(Dd / 128, Mm / 128);          // (8, 32)
    proj_mma<<<gProj, 256>>>(query, w_q, b_q, pQ);
    proj_mma<<<gProj, 256>>>(key,   w_k, b_k, pK);
    proj_mma<<<gProj, 256>>>(value, w_v, b_v, pV);

    dim3 gQrel((Rr + 127) / 128, BHS / 128); // (3, 512)
    qrel_mma<<<gQrel, 256>>>(rel_k);

    dim3 gScores(Ss / 128, Ss / 128, BHh);   // (8, 8, 64)
    scores_mma<<<gScores, 256>>>(mask);

    dim3 gCtx(Ss / 128, BHh);                // (8, 64)
    fctx_mma<<<gCtx, 128>>>(rel_v);

    dim3 gOut(Dd / 128, Mm / 128);           // (8, 32)
    outproj_mma<<<gOut, 256>>>(w_o, b_o, out);
}

// round 14
// speedup vs baseline: 1.5656x; 1.5656x over previous
#include <cuda_runtime.h>
#include <math.h>
#include <stdint.h>

// Problem constants
#define Bb   4
#define Ss   1024
#define Dd   1024
#define Hh   16
#define DKk  64
#define Rr   257          // 2*MAX_REL + 1
#define BHh  64           // B*H
#define Mm   4096         // B*S
#define BHS  65536        // B*H*S
#define SCALEF 0.125f     // 1/sqrt(64)
#define KC   32           // k-chunk
#define PKC  16           // packed k-chunk (bf16 pairs)
#define PKP  20           // padded packed stride (80B rows: 16B-aligned for ldmatrix, conflict-free)
#define PKP2 17           // scalar-load stride (fctx B)

// ---------------- scratch (device globals; no runtime allocation) ----------------
__device__ float g_Q[BHS * DKk];
__device__ float g_K[BHS * DKk];
__device__ float g_V[BHS * DKk];
__device__ float g_ctx[BHS * DKk];
__device__ float g_Qrel[BHS * Rr];
__device__ float g_arel[BHS * Rr];
__device__ float g_attn[67108864];        // [B,H,S,S] scores
__device__ float2 g_part[BHS * 8];        // per-(row, r-tile) softmax partials

// ---------------- split-bf16 helpers ----------------
__device__ __forceinline__ void split2(float x0, float x1, uint32_t& h, uint32_t& l) {
    uint32_t hp;
    asm("cvt.rn.bf16x2.f32 %0, %1, %2;" : "=r"(hp) : "f"(x1), "f"(x0));
    float h0 = __uint_as_float(hp << 16);
    float h1 = __uint_as_float(hp & 0xffff0000u);
    float r0 = x0 - h0, r1 = x1 - h1;
    uint32_t lp;
    asm("cvt.rn.bf16x2.f32 %0, %1, %2;" : "=r"(lp) : "f"(r1), "f"(r0));
    h = hp; l = lp;
}
__device__ __forceinline__ void mma_bf16(float* c, const uint32_t* a, const uint32_t* b) {
    asm volatile(
        "mma.sync.aligned.m16n8k16.row.col.f32.bf16.bf16.f32 "
        "{%0,%1,%2,%3}, {%4,%5,%6,%7}, {%8,%9}, {%0,%1,%2,%3};\n"
        : "+f"(c[0]), "+f"(c[1]), "+f"(c[2]), "+f"(c[3])
        : "r"(a[0]), "r"(a[1]), "r"(a[2]), "r"(a[3]), "r"(b[0]), "r"(b[1]));
}
__device__ __forceinline__ void ldsm_x4(uint32_t& r0, uint32_t& r1, uint32_t& r2,
                                        uint32_t& r3, uint32_t addr) {
    asm volatile("ldmatrix.sync.aligned.m8n8.x4.shared.b16 {%0,%1,%2,%3}, [%4];"
                 : "=r"(r0), "=r"(r1), "=r"(r2), "=r"(r3) : "r"(addr));
}
__device__ __forceinline__ void cpa16(void* dst, const void* src) {
    uint32_t s = (uint32_t)__cvta_generic_to_shared(dst);
    asm volatile("cp.async.ca.shared.global [%0], [%1], 16;" :: "r"(s), "l"(src));
}
#define CP_WAIT() do { asm volatile("cp.async.commit_group;\ncp.async.wait_group 0;" ::: "memory"); } while (0)

// ldmatrix-fed split-bf16 chunk (A + B via LDSM; both [row][pk], stride PKP).
#define MMA_CHUNK_LDSM()                                                         \
    _Pragma("unroll")                                                            \
    for (int ks2 = 0; ks2 < PKC; ks2 += 8) {                                     \
        uint32_t ah[4][4], al[4][4], bh[4][2], bl[4][2];                         \
        _Pragma("unroll")                                                        \
        for (int mt = 0; mt < 4; mt++) {                                         \
            uint32_t ra = (uint32_t)(((warp_m * 64 + mt * 16 + lq + ls1 * 8) * PKP \
                                      + ks2 + ls2 * 4) * 4);                     \
            ldsm_x4(ah[mt][0], ah[mt][1], ah[mt][2], ah[mt][3], uAh + ra);       \
            ldsm_x4(al[mt][0], al[mt][1], al[mt][2], al[mt][3], uAl + ra);       \
        }                                                                        \
        _Pragma("unroll")                                                        \
        for (int nt = 0; nt < 4; nt++) {                                         \
            uint32_t rb = (uint32_t)(((warp_n * 32 + nt * 8 + lq) * PKP          \
                                      + ks2 + ls1 * 4) * 4);                     \
            ldsm_x4(bh[nt][0], bh[nt][1], bl[nt][0], bl[nt][1], uBsel + rb);     \
        }                                                                        \
        _Pragma("unroll")                                                        \
        for (int mt = 0; mt < 4; mt++)                                           \
            _Pragma("unroll")                                                    \
            for (int nt = 0; nt < 4; nt++) {                                     \
                mma_bf16(c[mt][nt], ah[mt], bh[nt]);                             \
                mma_bf16(c[mt][nt], ah[mt], bl[nt]);                             \
                mma_bf16(c[mt][nt], al[mt], bh[nt]);                             \
            }                                                                    \
    }

// fctx variant: A via LDSM (stride PKP), B scalar (stride PKP2)
#define MMA_CHUNK_LDSM_A(BH_, BL_)                                               \
    _Pragma("unroll")                                                            \
    for (int ks2 = 0; ks2 < PKC; ks2 += 8) {                                     \
        uint32_t ah[4][4], al[4][4], bh[4][2], bl[4][2];                         \
        _Pragma("unroll")                                                        \
        for (int mt = 0; mt < 4; mt++) {                                         \
            uint32_t ra = (uint32_t)(((warp_m * 64 + mt * 16 + lq + ls1 * 8) * PKP \
                                      + ks2 + ls2 * 4) * 4);                     \
            ldsm_x4(ah[mt][0], ah[mt][1], ah[mt][2], ah[mt][3], uAh + ra);       \
            ldsm_x4(al[mt][0], al[mt][1], al[mt][2], al[mt][3], uAl + ra);       \
        }                                                                        \
        _Pragma("unroll")                                                        \
        for (int nt = 0; nt < 4; nt++) {                                         \
            int col = warp_n * 32 + nt * 8;                                      \
            bh[nt][0] = BH_[col + g][ks2 + tg];                                  \
            bh[nt][1] = BH_[col + g][ks2 + 4 + tg];                              \
            bl[nt][0] = BL_[col + g][ks2 + tg];                                  \
            bl[nt][1] = BL_[col + g][ks2 + 4 + tg];                              \
        }                                                                        \
        _Pragma("unroll")                                                        \
        for (int mt = 0; mt < 4; mt++)                                           \
            _Pragma("unroll")                                                    \
            for (int nt = 0; nt < 4; nt++) {                                     \
                mma_bf16(c[mt][nt], ah[mt], bh[nt]);                             \
                mma_bf16(c[mt][nt], ah[mt], bl[nt]);                             \
                mma_bf16(c[mt][nt], al[mt], bh[nt]);                             \
            }                                                                    \
    }

// =================================================================================
// Kernel 1: QKV projection. grid (8, 32), 256 threads (2m x 4n warps)
// =================================================================================
__global__ __launch_bounds__(256, 2) void proj_mma(const float* __restrict__ X,
                                                   const float* __restrict__ W,
                                                   const float* __restrict__ bias,
                                                   float* __restrict__ out)
{
    __shared__ uint32_t Ahp[128][PKP], Alp[128][PKP];
    __shared__ uint32_t Bhp[128][PKP], Blp[128][PKP];
    int n0 = blockIdx.x * 128, m0 = blockIdx.y * 128;
    int tid = threadIdx.x, warp = tid >> 5, lane = tid & 31;
    int warp_m = warp >> 2, warp_n = warp & 3;
    int lq = lane & 7, ls1 = (lane >> 3) & 1, ls2 = lane >> 4;
    uint32_t uAh = (uint32_t)__cvta_generic_to_shared(Ahp);
    uint32_t uAl = (uint32_t)__cvta_generic_to_shared(Alp);
    uint32_t uBh = (uint32_t)__cvta_generic_to_shared(Bhp);
    uint32_t uBl = (uint32_t)__cvta_generic_to_shared(Blp);
    uint32_t uBsel = (lane < 16) ? uBh : uBl;
    float c[4][4][4] = {};

    for (int k0 = 0; k0 < Dd; k0 += KC) {
        for (int i = tid; i < 2048; i += 256) {
            int r = i >> 4, pc = i & 15;
            float2 a = *(const float2*)&X[(size_t)(m0 + r) * Dd + k0 + 2 * pc];
            split2(a.x, a.y, Ahp[r][pc], Alp[r][pc]);
            float2 b = *(const float2*)&W[(size_t)(n0 + r) * Dd + k0 + 2 * pc];
            split2(b.x, b.y, Bhp[r][pc], Blp[r][pc]);
        }
        __syncthreads();
        MMA_CHUNK_LDSM()
        __syncthreads();
    }
    #pragma unroll
    for (int mt = 0; mt < 4; mt++)
        #pragma unroll
        for (int rr = 0; rr < 2; rr++) {
            int m = m0 + warp_m * 64 + mt * 16 + (lane >> 2) + rr * 8;
            int b = m >> 10, s = m & 1023;
            #pragma unroll
            for (int nt = 0; nt < 4; nt++) {
                int n = n0 + warp_n * 32 + nt * 8 + (lane & 3) * 2;
                float v0 = c[mt][nt][rr * 2 + 0] + bias[n];
                float v1 = c[mt][nt][rr * 2 + 1] + bias[n + 1];
                out[((b * Hh + (n >> 6)) * Ss + s) * DKk + (n & 63)] = v0;
                int n1 = n + 1;
                out[((b * Hh + (n1 >> 6)) * Ss + s) * DKk + (n1 & 63)] = v1;
            }
        }
}

// =================================================================================
// Kernel 2: Qrel. grid (3, 512)
// =================================================================================
__global__ __launch_bounds__(256, 2) void qrel_mma(const float* __restrict__ relk)
{
    __shared__ uint32_t Ahp[128][PKP], Alp[128][PKP];
    __shared__ uint32_t Bhp[128][PKP], Blp[128][PKP];
    int n0 = blockIdx.x * 128, m0 = blockIdx.y * 128;
    int tid = threadIdx.x, warp = tid >> 5, lane = tid & 31;
    int warp_m = warp >> 2, warp_n = warp & 3;
    int lq = lane & 7, ls1 = (lane >> 3) & 1, ls2 = lane >> 4;
    uint32_t uAh = (uint32_t)__cvta_generic_to_shared(Ahp);
    uint32_t uAl = (uint32_t)__cvta_generic_to_shared(Alp);
    uint32_t uBh = (uint32_t)__cvta_generic_to_shared(Bhp);
    uint32_t uBl = (uint32_t)__cvta_generic_to_shared(Blp);
    uint32_t uBsel = (lane < 16) ? uBh : uBl;
    float c[4][4][4] = {};

    for (int k0 = 0; k0 < DKk; k0 += KC) {
        for (int i = tid; i < 2048; i += 256) {
            int r = i >> 4, pc = i & 15;
            float2 a = *(const float2*)&g_Q[(size_t)(m0 + r) * DKk + k0 + 2 * pc];
            split2(a.x, a.y, Ahp[r][pc], Alp[r][pc]);
            float2 b = make_float2(0.f, 0.f);
            if (n0 + r < Rr) b = *(const float2*)&relk[(size_t)(n0 + r) * DKk + k0 + 2 * pc];
            split2(b.x, b.y, Bhp[r][pc], Blp[r][pc]);
        }
        __syncthreads();
        MMA_CHUNK_LDSM()
        __syncthreads();
    }
    #pragma unroll
    for (int mt = 0; mt < 4; mt++)
        #pragma unroll
        for (int rr = 0; rr < 2; rr++) {
            int m = m0 + warp_m * 64 + mt * 16 + (lane >> 2) + rr * 8;
            #pragma unroll
            for (int nt = 0; nt < 4; nt++) {
                int n = n0 + warp_n * 32 + nt * 8 + (lane & 3) * 2;
                if (n < Rr)     g_Qrel[(size_t)m * Rr + n]     = c[mt][nt][rr * 2 + 0];
                if (n + 1 < Rr) g_Qrel[(size_t)m * Rr + n + 1] = c[mt][nt][rr * 2 + 1];
            }
        }
}

// =================================================================================
// Kernel 3: scores + rel-K gather + mask -> g_attn + softmax partials -> g_part
// grid (8, 8, 64), 256 threads
// =================================================================================
__global__ __launch_bounds__(256, 2) void scores_mma(const int* __restrict__ mask)
{
    __shared__ uint32_t Ahp[128][PKP], Alp[128][PKP];
    __shared__ uint32_t Bhp[128][PKP], Blp[128][PKP];
    __shared__ float redm[4][128];
    __shared__ float reds[4][128];
    __shared__ int msk[128];
    int z = blockIdx.z;
    int r0 = blockIdx.x * 128, l0 = blockIdx.y * 128;
    const float* Qb = g_Q + (size_t)z * Ss * DKk;
    const float* Kb = g_K + (size_t)z * Ss * DKk;
    int tid = threadIdx.x, warp = tid >> 5, lane = tid & 31;
    int warp_m = warp >> 2, warp_n = warp & 3;
    int g = lane >> 2, tg = lane & 3;
    int lq = lane & 7, ls1 = (lane >> 3) & 1, ls2 = lane >> 4;
    uint32_t uAh = (uint32_t)__cvta_generic_to_shared(Ahp);
    uint32_t uAl = (uint32_t)__cvta_generic_to_shared(Alp);
    uint32_t uBh = (uint32_t)__cvta_generic_to_shared(Bhp);
    uint32_t uBl = (uint32_t)__cvta_generic_to_shared(Blp);
    uint32_t uBsel = (lane < 16) ? uBh : uBl;
    float c[4][4][4] = {};

    if (tid < 128) msk[tid] = mask[(z >> 4) * Ss + r0 + tid];

    for (int k0 = 0; k0 < DKk; k0 += KC) {
        for (int i = tid; i < 2048; i += 256) {
            int r = i >> 4, pc = i & 15;
            float2 a = *(const float2*)&Qb[(size_t)(l0 + r) * DKk + k0 + 2 * pc];
            split2(a.x, a.y, Ahp[r][pc], Alp[r][pc]);
            float2 b = *(const float2*)&Kb[(size_t)(r0 + r) * DKk + k0 + 2 * pc];
            split2(b.x, b.y, Bhp[r][pc], Blp[r][pc]);
        }
        __syncthreads();
        MMA_CHUNK_LDSM()
        __syncthreads();
    }
    // epilogue: finalize scores in-place, write to g_attn, per-row tile max
    #pragma unroll
    for (int mt = 0; mt < 4; mt++)
        #pragma unroll
        for (int rr = 0; rr < 2; rr++) {
            int row_local = warp_m * 64 + mt * 16 + rr * 8 + g;
            int l = l0 + row_local;
            const float* qr = &g_Qrel[(size_t)(z * Ss + l) * Rr];
            float* arow = &g_attn[(size_t)(z * Ss + l) * Ss];
            float vmax = -INFINITY;
            #pragma unroll
            for (int nt = 0; nt < 4; nt++) {
                int r = r0 + warp_n * 32 + nt * 8 + tg * 2;
                #pragma unroll
                for (int e = 0; e < 2; e++) {
                    int rc = r + e;
                    float sc = c[mt][nt][rr * 2 + e] * SCALEF;
                    int rel = rc - l;
                    rel = rel < -128 ? -128 : (rel > 128 ? 128 : rel);
                    sc += qr[rel + 128];
                    if (msk[rc - r0] == 0) sc = -1000000000.0f;
                    c[mt][nt][rr * 2 + e] = sc;
                    arow[rc] = sc;
                    vmax = fmaxf(vmax, sc);
                }
            }
            vmax = fmaxf(vmax, __shfl_xor_sync(0xffffffffu, vmax, 1));
            vmax = fmaxf(vmax, __shfl_xor_sync(0xffffffffu, vmax, 2));
            if (tg == 0) redm[warp_n][row_local] = vmax;
        }
    __syncthreads();
    #pragma unroll
    for (int mt = 0; mt < 4; mt++)
        #pragma unroll
        for (int rr = 0; rr < 2; rr++) {
            int row_local = warp_m * 64 + mt * 16 + rr * 8 + g;
            float tmax = fmaxf(fmaxf(redm[0][row_local], redm[1][row_local]),
                               fmaxf(redm[2][row_local], redm[3][row_local]));
            float s = 0.f;
            #pragma unroll
            for (int nt = 0; nt < 4; nt++)
                #pragma unroll
                for (int e = 0; e < 2; e++)
                    s += expf(c[mt][nt][rr * 2 + e] - tmax);
            s += __shfl_xor_sync(0xffffffffu, s, 1);
            s += __shfl_xor_sync(0xffffffffu, s, 2);
            if (tg == 0) reds[warp_n][row_local] = s;
        }
    __syncthreads();
    if (tid < 128) {
        float tm = fmaxf(fmaxf(redm[0][tid], redm[1][tid]),
                         fmaxf(redm[2][tid], redm[3][tid]));
        float Zt = reds[0][tid] + reds[1][tid] + reds[2][tid] + reds[3][tid];
        g_part[((size_t)z * Ss + l0 + tid) * 8 + blockIdx.x] = make_float2(tm, Zt);
    }
}

// =================================================================================
// Kernel 4 (fused softmax + context). grid (8, 64), 128 threads (thread == l-row)
// =================================================================================
__global__ __launch_bounds__(128, 4) void fctx_mma(const float* __restrict__ relv)
{
    __shared__ float Sf[128][36];              // fp32 score staging (144B rows: 16B-aligned)
    __shared__ uint32_t Ahp[128][PKP], Alp[128][PKP];
    __shared__ uint32_t Bhp[64][PKP2], Blp[64][PKP2];
    int z = blockIdx.y;
    int l0 = blockIdx.x * 128;
    int tid = threadIdx.x, warp = tid >> 5, lane = tid & 31;
    int warp_m = warp >> 1, warp_n = warp & 1;
    int g = lane >> 2, tg = lane & 3;
    int lq = lane & 7, ls1 = (lane >> 3) & 1, ls2 = lane >> 4;
    uint32_t uAh = (uint32_t)__cvta_generic_to_shared(Ahp);
    uint32_t uAl = (uint32_t)__cvta_generic_to_shared(Alp);
    const float* Vb = g_V + (size_t)z * Ss * DKk;
    float c[4][4][4] = {};

    // --- per-row softmax stats ---
    int l = l0 + tid;
    float m = -INFINITY, Z = 0.f;
    {
        const float2* pp = &g_part[((size_t)z * Ss + l) * 8];
        float2 v[8];
        #pragma unroll
        for (int i = 0; i < 8; i++) { v[i] = pp[i]; m = fmaxf(m, v[i].x); }
        #pragma unroll
        for (int i = 0; i < 8; i++) Z += v[i].y * expf(v[i].x - m);
    }
    float invZ = 1.f / Z;
    float* arow = &g_arel[(size_t)(z * Ss + l) * Rr];
    for (int p = 1; p <= 127 - l; p++) arow[p] = 0.f;
    for (int p = 1152 - l; p <= 255; p++) arow[p] = 0.f;
    float p0a = 0.f, p256a = 0.f;

    // --- streaming pass: scores tile -> probs (packed bf16) -> arel + PV MMA ---
    for (int r0 = 0; r0 < Ss; r0 += KC) {
        for (int i = tid; i < 1024; i += 128) {
            int r = i >> 3, c4 = (i & 7) * 4;
            cpa16(&Sf[r][c4], &g_attn[(size_t)(z * Ss + l0 + r) * Ss + r0 + c4]);
        }
        for (int i = tid; i < 1024; i += 128) {
            int d = i & 63, pk = i >> 6;
            float v0 = Vb[(size_t)(r0 + 2 * pk) * DKk + d];
            float v1 = Vb[(size_t)(r0 + 2 * pk + 1) * DKk + d];
            split2(v0, v1, Bhp[d][pk], Blp[d][pk]);
        }
        CP_WAIT();
        __syncthreads();
        #pragma unroll
        for (int pc = 0; pc < PKC; pc++) {
            float s0 = Sf[tid][2 * pc], s1 = Sf[tid][2 * pc + 1];
            float p0f = expf(s0 - m) * invZ;
            float p1f = expf(s1 - m) * invZ;
            int rel0 = r0 + 2 * pc - l;
            if (rel0 <= -128) p0a += p0f;
            else if (rel0 >= 128) p256a += p0f;
            else arow[rel0 + 128] = p0f;
            int rel1 = rel0 + 1;
            if (rel1 <= -128) p0a += p1f;
            else if (rel1 >= 128) p256a += p1f;
            else arow[rel1 + 128] = p1f;
            split2(p0f, p1f, Ahp[tid][pc], Alp[tid][pc]);
        }
        __syncthreads();
        MMA_CHUNK_LDSM_A(Bhp, Blp)
        __syncthreads();
    }
    arow[0] = p0a;
    arow[256] = p256a;
    __syncthreads();

    // --- rel-value part: K = 257 in zero-padded chunks ---
    for (int p0 = 0; p0 < Rr; p0 += KC) {
        for (int i = tid; i < 2048; i += 128) {
            int r = i >> 4, pc = i & 15;
            int p = p0 + 2 * pc;
            float a0 = (p     < Rr) ? g_arel[(size_t)(z * Ss + l0 + r) * Rr + p]     : 0.f;
            float a1 = (p + 1 < Rr) ? g_arel[(size_t)(z * Ss + l0 + r) * Rr + p + 1] : 0.f;
            split2(a0, a1, Ahp[r][pc], Alp[r][pc]);
        }
        for (int i = tid; i < 1024; i += 128) {
            int d = i & 63, pk = i >> 6;
            int p = p0 + 2 * pk;
            float v0 = (p     < Rr) ? relv[(size_t)p * DKk + d]       : 0.f;
            float v1 = (p + 1 < Rr) ? relv[(size_t)(p + 1) * DKk + d] : 0.f;
            split2(v0, v1, Bhp[d][pk], Blp[d][pk]);
        }
        __syncthreads();
        MMA_CHUNK_LDSM_A(Bhp, Blp)
        __syncthreads();
    }
    #pragma unroll
    for (int mt = 0; mt < 4; mt++)
        #pragma unroll
        for (int rr = 0; rr < 2; rr++) {
            int lr = l0 + warp_m * 64 + mt * 16 + g + rr * 8;
            #pragma unroll
            for (int nt = 0; nt < 4; nt++) {
                int d = warp_n * 32 + nt * 8 + tg * 2;
                g_ctx[(size_t)(z * Ss + lr) * DKk + d]     = c[mt][nt][rr * 2 + 0];
                g_ctx[(size_t)(z * Ss + lr) * DKk + d + 1] = c[mt][nt][rr * 2 + 1];
            }
        }
}

// =================================================================================
// Kernel 5: outproj. grid (8, 32), 256 threads
// =================================================================================
__global__ __launch_bounds__(256, 2) void outproj_mma(const float* __restrict__ Wo,
                                                      const float* __restrict__ bo,
                                                      float* __restrict__ out)
{
    __shared__ uint32_t Ahp[128][PKP], Alp[128][PKP];
    __shared__ uint32_t Bhp[128][PKP], Blp[128][PKP];
    int n0 = blockIdx.x * 128, m0 = blockIdx.y * 128;
    int tid = threadIdx.x, warp = tid >> 5, lane = tid & 31;
    int warp_m = warp >> 2, warp_n = warp & 3;
    int lq = lane & 7, ls1 = (lane >> 3) & 1, ls2 = lane >> 4;
    uint32_t uAh = (uint32_t)__cvta_generic_to_shared(Ahp);
    uint32_t uAl = (uint32_t)__cvta_generic_to_shared(Alp);
    uint32_t uBh = (uint32_t)__cvta_generic_to_shared(Bhp);
    uint32_t uBl = (uint32_t)__cvta_generic_to_shared(Blp);
    uint32_t uBsel = (lane < 16) ? uBh : uBl;
    float c[4][4][4] = {};

    for (int k0 = 0; k0 < Dd; k0 += KC) {
        int h = k0 >> 6, dk0 = k0 & 63;
        for (int i = tid; i < 2048; i += 256) {
            int r = i >> 4, pc = i & 15;
            int mm = m0 + r, b = mm >> 10, s = mm & 1023;
            float2 a = *(const float2*)&g_ctx[(size_t)((b * Hh + h) * Ss + s) * DKk + dk0 + 2 * pc];
            split2(a.x, a.y, Ahp[r][pc], Alp[r][pc]);
            float2 w = *(const float2*)&Wo[(size_t)(n0 + r) * Dd + k0 + 2 * pc];
            split2(w.x, w.y, Bhp[r][pc], Blp[r][pc]);
        }
        __syncthreads();
        MMA_CHUNK_LDSM()
        __syncthreads();
    }
    #pragma unroll
    for (int mt = 0; mt < 4; mt++)
        #pragma unroll
        for (int rr = 0; rr < 2; rr++) {
            int mm = m0 + warp_m * 64 + mt * 16 + (lane >> 2) + rr * 8;
            #pragma unroll
            for (int nt = 0; nt < 4; nt++) {
                int n = n0 + warp_n * 32 + nt * 8 + (lane & 3) * 2;
                out[(size_t)mm * Dd + n]     = c[mt][nt][rr * 2 + 0] + bo[n];
                out[(size_t)mm * Dd + n + 1] = c[mt][nt][rr * 2 + 1] + bo[n + 1];
            }
        }
}

extern "C" void kernel_launch(void* const* d_in, const int* in_sizes, int n_in,
                              void* d_out, int out_size)
{
    const float* query = (const float*)d_in[0];
    const float* key   = (const float*)d_in[1];
    const float* value = (const float*)d_in[2];
    const int*   mask  = (const int*)  d_in[3];
    const float* w_q   = (const float*)d_in[4];
    const float* b_q   = (const float*)d_in[5];
    const float* w_k   = (const float*)d_in[6];
    const float* b_k   = (const float*)d_in[7];
    const float* w_v   = (const float*)d_in[8];
    const float* b_v   = (const float*)d_in[9];
    const float* w_o   = (const float*)d_in[10];
    const float* b_o   = (const float*)d_in[11];
    const float* rel_k = (const float*)d_in[12];
    const float* rel_v = (const float*)d_in[13];
    float* out = (float*)d_out;

    float *pQ, *pK, *pV;
    cudaGetSymbolAddress((void**)&pQ, g_Q);
    cudaGetSymbolAddress((void**)&pK, g_K);
    cudaGetSymbolAddress((void**)&pV, g_V);

    dim3 gProj(Dd / 128, Mm / 128);          // (8, 32)
    proj_mma<<<gProj, 256>>>(query, w_q, b_q, pQ);
    proj_mma<<<gProj, 256>>>(key,   w_k, b_k, pK);
    proj_mma<<<gProj, 256>>>(value, w_v, b_v, pV);

    dim3 gQrel((Rr + 127) / 128, BHS / 128); // (3, 512)
    qrel_mma<<<gQrel, 256>>>(rel_k);

    dim3 gScores(Ss / 128, Ss / 128, BHh);   // (8, 8, 64)
    scores_mma<<<gScores, 256>>>(mask);

    dim3 gCtx(Ss / 128, BHh);                // (8, 64)
    fctx_mma<<<gCtx, 128>>>(rel_v);

    dim3 gOut(Dd / 128, Mm / 128);           // (8, 32)
    outproj_mma<<<gOut, 256>>>(w_o, b_o, out);
}

// round 15
// speedup vs baseline: 1.6878x; 1.0780x over previous
#include <cuda_runtime.h>
#include <math.h>
#include <stdint.h>

// Problem constants
#define Bb   4
#define Ss   1024
#define Dd   1024
#define Hh   16
#define DKk  64
#define Rr   257          // 2*MAX_REL + 1
#define BHh  64           // B*H
#define Mm   4096         // B*S
#define BHS  65536        // B*H*S
#define SCALEF 0.125f     // 1/sqrt(64)
#define KC   32           // k-chunk
#define PKC  16           // packed k-chunk (bf16 pairs)
#define PKP  20           // padded packed stride (80B rows: 16B-aligned for ldmatrix)
#define PKP2 17           // scalar-load stride (fctx B)
#define INP  2097152      // packed pairs per input tensor (4096*512)
#define WP   524288       // packed pairs per weight matrix (1024*512)

// ---------------- scratch (device globals; no runtime allocation) ----------------
__device__ uint32_t g_inh[3 * INP], g_inl[3 * INP];   // pre-split query/key/value
__device__ uint32_t g_wh[4 * WP],   g_wl[4 * WP];     // pre-split w_q/w_k/w_v/w_o
__device__ uint32_t g_rkh[8224],    g_rkl[8224];      // pre-split rel_k (257*32)
__device__ uint32_t g_Qh[INP], g_Ql[INP];             // packed Q  [BHS][32]
__device__ uint32_t g_Kh[INP], g_Kl[INP];             // packed K
__device__ uint32_t g_ch[INP], g_cl[INP];             // packed ctx
__device__ float    g_V[BHS * DKk];
__device__ float    g_Qrel[BHS * Rr];
__device__ float    g_arel[BHS * Rr];
__device__ float    g_attn[67108864];                 // [B,H,S,S] scores
__device__ float2   g_part[BHS * 8];                  // softmax partials

// ---------------- split-bf16 helpers ----------------
__device__ __forceinline__ void split2(float x0, float x1, uint32_t& h, uint32_t& l) {
    uint32_t hp;
    asm("cvt.rn.bf16x2.f32 %0, %1, %2;" : "=r"(hp) : "f"(x1), "f"(x0));
    float h0 = __uint_as_float(hp << 16);
    float h1 = __uint_as_float(hp & 0xffff0000u);
    float r0 = x0 - h0, r1 = x1 - h1;
    uint32_t lp;
    asm("cvt.rn.bf16x2.f32 %0, %1, %2;" : "=r"(lp) : "f"(r1), "f"(r0));
    h = hp; l = lp;
}
__device__ __forceinline__ void mma_bf16(float* c, const uint32_t* a, const uint32_t* b) {
    asm volatile(
        "mma.sync.aligned.m16n8k16.row.col.f32.bf16.bf16.f32 "
        "{%0,%1,%2,%3}, {%4,%5,%6,%7}, {%8,%9}, {%0,%1,%2,%3};\n"
        : "+f"(c[0]), "+f"(c[1]), "+f"(c[2]), "+f"(c[3])
        : "r"(a[0]), "r"(a[1]), "r"(a[2]), "r"(a[3]), "r"(b[0]), "r"(b[1]));
}
__device__ __forceinline__ void ldsm_x4(uint32_t& r0, uint32_t& r1, uint32_t& r2,
                                        uint32_t& r3, uint32_t addr) {
    asm volatile("ldmatrix.sync.aligned.m8n8.x4.shared.b16 {%0,%1,%2,%3}, [%4];"
                 : "=r"(r0), "=r"(r1), "=r"(r2), "=r"(r3) : "r"(addr));
}
__device__ __forceinline__ void cpa16(void* dst, const void* src) {
    uint32_t s = (uint32_t)__cvta_generic_to_shared(dst);
    asm volatile("cp.async.ca.shared.global [%0], [%1], 16;" :: "r"(s), "l"(src));
}
__device__ __forceinline__ void cpa16p(void* dst, const void* src, bool pred) {
    uint32_t s = (uint32_t)__cvta_generic_to_shared(dst);
    int sz = pred ? 16 : 0;   // sz=0 -> zero-fill destination
    asm volatile("cp.async.ca.shared.global [%0], [%1], 16, %2;" :: "r"(s), "l"(src), "r"(sz));
}
#define CP_WAIT() do { asm volatile("cp.async.commit_group;\ncp.async.wait_group 0;" ::: "memory"); } while (0)

// ldmatrix-fed split-bf16 chunk (A + B via LDSM; both [row][pk], stride PKP).
#define MMA_CHUNK_LDSM()                                                         \
    _Pragma("unroll")                                                            \
    for (int ks2 = 0; ks2 < PKC; ks2 += 8) {                                     \
        uint32_t ah[4][4], al[4][4], bh[4][2], bl[4][2];                         \
        _Pragma("unroll")                                                        \
        for (int mt = 0; mt < 4; mt++) {                                         \
            uint32_t ra = (uint32_t)(((warp_m * 64 + mt * 16 + lq + ls1 * 8) * PKP \
                                      + ks2 + ls2 * 4) * 4);                     \
            ldsm_x4(ah[mt][0], ah[mt][1], ah[mt][2], ah[mt][3], uAh + ra);       \
            ldsm_x4(al[mt][0], al[mt][1], al[mt][2], al[mt][3], uAl + ra);       \
        }                                                                        \
        _Pragma("unroll")                                                        \
        for (int nt = 0; nt < 4; nt++) {                                         \
            uint32_t rb = (uint32_t)(((warp_n * 32 + nt * 8 + lq) * PKP          \
                                      + ks2 + ls1 * 4) * 4);                     \
            ldsm_x4(bh[nt][0], bh[nt][1], bl[nt][0], bl[nt][1], uBsel + rb);     \
        }                                                                        \
        _Pragma("unroll")                                                        \
        for (int mt = 0; mt < 4; mt++)                                           \
            _Pragma("unroll")                                                    \
            for (int nt = 0; nt < 4; nt++) {                                     \
                mma_bf16(c[mt][nt], ah[mt], bh[nt]);                             \
                mma_bf16(c[mt][nt], ah[mt], bl[nt]);                             \
                mma_bf16(c[mt][nt], al[mt], bh[nt]);                             \
            }                                                                    \
    }

// fctx variant: A via LDSM (stride PKP), B scalar (stride PKP2)
#define MMA_CHUNK_LDSM_A(BH_, BL_)                                               \
    _Pragma("unroll")                                                            \
    for (int ks2 = 0; ks2 < PKC; ks2 += 8) {                                     \
        uint32_t ah[4][4], al[4][4], bh[4][2], bl[4][2];                         \
        _Pragma("unroll")                                                        \
        for (int mt = 0; mt < 4; mt++) {                                         \
            uint32_t ra = (uint32_t)(((warp_m * 64 + mt * 16 + lq + ls1 * 8) * PKP \
                                      + ks2 + ls2 * 4) * 4);                     \
            ldsm_x4(ah[mt][0], ah[mt][1], ah[mt][2], ah[mt][3], uAh + ra);       \
            ldsm_x4(al[mt][0], al[mt][1], al[mt][2], al[mt][3], uAl + ra);       \
        }                                                                        \
        _Pragma("unroll")                                                        \
        for (int nt = 0; nt < 4; nt++) {                                         \
            int col = warp_n * 32 + nt * 8;                                      \
            bh[nt][0] = BH_[col + g][ks2 + tg];                                  \
            bh[nt][1] = BH_[col + g][ks2 + 4 + tg];                              \
            bl[nt][0] = BL_[col + g][ks2 + tg];                                  \
            bl[nt][1] = BL_[col + g][ks2 + 4 + tg];                              \
        }                                                                        \
        _Pragma("unroll")                                                        \
        for (int mt = 0; mt < 4; mt++)                                           \
            _Pragma("unroll")                                                    \
            for (int nt = 0; nt < 4; nt++) {                                     \
                mma_bf16(c[mt][nt], ah[mt], bh[nt]);                             \
                mma_bf16(c[mt][nt], ah[mt], bl[nt]);                             \
                mma_bf16(c[mt][nt], al[mt], bh[nt]);                             \
            }                                                                    \
    }

// =================================================================================
// Kernel 0: presplit — fp32 pairs -> packed bf16 hi/lo (one elem converted ONCE)
// =================================================================================
__global__ __launch_bounds__(256) void presplit(const float* __restrict__ src,
                                                uint32_t* __restrict__ dh,
                                                uint32_t* __restrict__ dl, int n2)
{
    int i = blockIdx.x * 256 + threadIdx.x;
    if (i < n2) {
        float2 v = ((const float2*)src)[i];
        split2(v.x, v.y, dh[i], dl[i]);
    }
}

// =================================================================================
// Kernel 1: QKV projection from packed operands. grid (8, 32), 256 threads
// packed != 0: write packed hi/lo (Q, K). packed == 0: write fp32 (V).
// =================================================================================
__global__ __launch_bounds__(256, 2) void proj_mma(const uint32_t* __restrict__ Xh,
                                                   const uint32_t* __restrict__ Xl,
                                                   const uint32_t* __restrict__ Wh,
                                                   const uint32_t* __restrict__ Wl,
                                                   const float* __restrict__ bias,
                                                   uint32_t* __restrict__ outh,
                                                   uint32_t* __restrict__ outl,
                                                   float* __restrict__ outf, int packed)
{
    __shared__ uint32_t Ahp[128][PKP], Alp[128][PKP];
    __shared__ uint32_t Bhp[128][PKP], Blp[128][PKP];
    int n0 = blockIdx.x * 128, m0 = blockIdx.y * 128;
    int tid = threadIdx.x, warp = tid >> 5, lane = tid & 31;
    int warp_m = warp >> 2, warp_n = warp & 3;
    int lq = lane & 7, ls1 = (lane >> 3) & 1, ls2 = lane >> 4;
    uint32_t uAh = (uint32_t)__cvta_generic_to_shared(Ahp);
    uint32_t uAl = (uint32_t)__cvta_generic_to_shared(Alp);
    uint32_t uBh = (uint32_t)__cvta_generic_to_shared(Bhp);
    uint32_t uBl = (uint32_t)__cvta_generic_to_shared(Blp);
    uint32_t uBsel = (lane < 16) ? uBh : uBl;
    float c[4][4][4] = {};

    for (int k0 = 0; k0 < Dd; k0 += KC) {
        int pk0 = k0 >> 1;
        for (int i = tid; i < 512; i += 256) {
            int r = i >> 2, p4 = (i & 3) << 2;
            cpa16(&Ahp[r][p4], &Xh[(size_t)(m0 + r) * 512 + pk0 + p4]);
            cpa16(&Alp[r][p4], &Xl[(size_t)(m0 + r) * 512 + pk0 + p4]);
            cpa16(&Bhp[r][p4], &Wh[(size_t)(n0 + r) * 512 + pk0 + p4]);
            cpa16(&Blp[r][p4], &Wl[(size_t)(n0 + r) * 512 + pk0 + p4]);
        }
        CP_WAIT();
        __syncthreads();
        MMA_CHUNK_LDSM()
        __syncthreads();
    }
    #pragma unroll
    for (int mt = 0; mt < 4; mt++)
        #pragma unroll
        for (int rr = 0; rr < 2; rr++) {
            int m = m0 + warp_m * 64 + mt * 16 + (lane >> 2) + rr * 8;
            int b = m >> 10, s = m & 1023;
            #pragma unroll
            for (int nt = 0; nt < 4; nt++) {
                int n = n0 + warp_n * 32 + nt * 8 + (lane & 3) * 2;
                float v0 = c[mt][nt][rr * 2 + 0] + bias[n];
                float v1 = c[mt][nt][rr * 2 + 1] + bias[n + 1];
                size_t base = ((size_t)(b * Hh + (n >> 6)) * Ss + s);
                if (packed) {
                    uint32_t hh, ll;
                    split2(v0, v1, hh, ll);
                    size_t idx = base * 32 + ((n & 63) >> 1);
                    outh[idx] = hh; outl[idx] = ll;
                } else {
                    outf[base * DKk + (n & 63)]     = v0;
                    outf[base * DKk + (n & 63) + 1] = v1;
                }
            }
        }
}

// =================================================================================
// Kernel 2: Qrel (packed Q x packed rel_k). grid (3, 512)
// =================================================================================
__global__ __launch_bounds__(256, 2) void qrel_mma()
{
    __shared__ uint32_t Ahp[128][PKP], Alp[128][PKP];
    __shared__ uint32_t Bhp[128][PKP], Blp[128][PKP];
    int n0 = blockIdx.x * 128, m0 = blockIdx.y * 128;
    int tid = threadIdx.x, warp = tid >> 5, lane = tid & 31;
    int warp_m = warp >> 2, warp_n = warp & 3;
    int lq = lane & 7, ls1 = (lane >> 3) & 1, ls2 = lane >> 4;
    uint32_t uAh = (uint32_t)__cvta_generic_to_shared(Ahp);
    uint32_t uAl = (uint32_t)__cvta_generic_to_shared(Alp);
    uint32_t uBh = (uint32_t)__cvta_generic_to_shared(Bhp);
    uint32_t uBl = (uint32_t)__cvta_generic_to_shared(Blp);
    uint32_t uBsel = (lane < 16) ? uBh : uBl;
    float c[4][4][4] = {};

    for (int k0 = 0; k0 < DKk; k0 += KC) {
        int pk0 = k0 >> 1;
        for (int i = tid; i < 512; i += 256) {
            int r = i >> 2, p4 = (i & 3) << 2;
            cpa16(&Ahp[r][p4], &g_Qh[(size_t)(m0 + r) * 32 + pk0 + p4]);
            cpa16(&Alp[r][p4], &g_Ql[(size_t)(m0 + r) * 32 + pk0 + p4]);
            bool ok = (n0 + r) < Rr;
            size_t bi = ok ? ((size_t)(n0 + r) * 32 + pk0 + p4) : 0;
            cpa16p(&Bhp[r][p4], &g_rkh[bi], ok);
            cpa16p(&Blp[r][p4], &g_rkl[bi], ok);
        }
        CP_WAIT();
        __syncthreads();
        MMA_CHUNK_LDSM()
        __syncthreads();
    }
    #pragma unroll
    for (int mt = 0; mt < 4; mt++)
        #pragma unroll
        for (int rr = 0; rr < 2; rr++) {
            int m = m0 + warp_m * 64 + mt * 16 + (lane >> 2) + rr * 8;
            #pragma unroll
            for (int nt = 0; nt < 4; nt++) {
                int n = n0 + warp_n * 32 + nt * 8 + (lane & 3) * 2;
                if (n < Rr)     g_Qrel[(size_t)m * Rr + n]     = c[mt][nt][rr * 2 + 0];
                if (n + 1 < Rr) g_Qrel[(size_t)m * Rr + n + 1] = c[mt][nt][rr * 2 + 1];
            }
        }
}

// =================================================================================
// Kernel 3: scores (packed Q x packed K) + rel-K gather + mask + softmax partials
// grid (8, 8, 64), 256 threads
// =================================================================================
__global__ __launch_bounds__(256, 2) void scores_mma(const int* __restrict__ mask)
{
    __shared__ uint32_t Ahp[128][PKP], Alp[128][PKP];
    __shared__ uint32_t Bhp[128][PKP], Blp[128][PKP];
    __shared__ float redm[4][128];
    __shared__ float reds[4][128];
    __shared__ int msk[128];
    int z = blockIdx.z;
    int r0 = blockIdx.x * 128, l0 = blockIdx.y * 128;
    int tid = threadIdx.x, warp = tid >> 5, lane = tid & 31;
    int warp_m = warp >> 2, warp_n = warp & 3;
    int g = lane >> 2, tg = lane & 3;
    int lq = lane & 7, ls1 = (lane >> 3) & 1, ls2 = lane >> 4;
    uint32_t uAh = (uint32_t)__cvta_generic_to_shared(Ahp);
    uint32_t uAl = (uint32_t)__cvta_generic_to_shared(Alp);
    uint32_t uBh = (uint32_t)__cvta_generic_to_shared(Bhp);
    uint32_t uBl = (uint32_t)__cvta_generic_to_shared(Blp);
    uint32_t uBsel = (lane < 16) ? uBh : uBl;
    float c[4][4][4] = {};
    size_t zb = (size_t)z * Ss * 32;

    if (tid < 128) msk[tid] = mask[(z >> 4) * Ss + r0 + tid];

    for (int k0 = 0; k0 < DKk; k0 += KC) {
        int pk0 = k0 >> 1;
        for (int i = tid; i < 512; i += 256) {
            int r = i >> 2, p4 = (i & 3) << 2;
            cpa16(&Ahp[r][p4], &g_Qh[zb + (size_t)(l0 + r) * 32 + pk0 + p4]);
            cpa16(&Alp[r][p4], &g_Ql[zb + (size_t)(l0 + r) * 32 + pk0 + p4]);
            cpa16(&Bhp[r][p4], &g_Kh[zb + (size_t)(r0 + r) * 32 + pk0 + p4]);
            cpa16(&Blp[r][p4], &g_Kl[zb + (size_t)(r0 + r) * 32 + pk0 + p4]);
        }
        CP_WAIT();
        __syncthreads();
        MMA_CHUNK_LDSM()
        __syncthreads();
    }
    // epilogue: finalize scores in-place, write to g_attn, per-row tile max
    #pragma unroll
    for (int mt = 0; mt < 4; mt++)
        #pragma unroll
        for (int rr = 0; rr < 2; rr++) {
            int row_local = warp_m * 64 + mt * 16 + rr * 8 + g;
            int l = l0 + row_local;
            const float* qr = &g_Qrel[(size_t)(z * Ss + l) * Rr];
            float* arow = &g_attn[(size_t)(z * Ss + l) * Ss];
            float vmax = -INFINITY;
            #pragma unroll
            for (int nt = 0; nt < 4; nt++) {
                int r = r0 + warp_n * 32 + nt * 8 + tg * 2;
                #pragma unroll
                for (int e = 0; e < 2; e++) {
                    int rc = r + e;
                    float sc = c[mt][nt][rr * 2 + e] * SCALEF;
                    int rel = rc - l;
                    rel = rel < -128 ? -128 : (rel > 128 ? 128 : rel);
                    sc += qr[rel + 128];
                    if (msk[rc - r0] == 0) sc = -1000000000.0f;
                    c[mt][nt][rr * 2 + e] = sc;
                    arow[rc] = sc;
                    vmax = fmaxf(vmax, sc);
                }
            }
            vmax = fmaxf(vmax, __shfl_xor_sync(0xffffffffu, vmax, 1));
            vmax = fmaxf(vmax, __shfl_xor_sync(0xffffffffu, vmax, 2));
            if (tg == 0) redm[warp_n][row_local] = vmax;
        }
    __syncthreads();
    #pragma unroll
    for (int mt = 0; mt < 4; mt++)
        #pragma unroll
        for (int rr = 0; rr < 2; rr++) {
            int row_local = warp_m * 64 + mt * 16 + rr * 8 + g;
            float tmax = fmaxf(fmaxf(redm[0][row_local], redm[1][row_local]),
                               fmaxf(redm[2][row_local], redm[3][row_local]));
            float s = 0.f;
            #pragma unroll
            for (int nt = 0; nt < 4; nt++)
                #pragma unroll
                for (int e = 0; e < 2; e++)
                    s += expf(c[mt][nt][rr * 2 + e] - tmax);
            s += __shfl_xor_sync(0xffffffffu, s, 1);
            s += __shfl_xor_sync(0xffffffffu, s, 2);
            if (tg == 0) reds[warp_n][row_local] = s;
        }
    __syncthreads();
    if (tid < 128) {
        float tm = fmaxf(fmaxf(redm[0][tid], redm[1][tid]),
                         fmaxf(redm[2][tid], redm[3][tid]));
        float Zt = reds[0][tid] + reds[1][tid] + reds[2][tid] + reds[3][tid];
        g_part[((size_t)z * Ss + l0 + tid) * 8 + blockIdx.x] = make_float2(tm, Zt);
    }
}

// =================================================================================
// Kernel 4 (fused softmax + context). grid (8, 64), 128 threads (thread == l-row)
// Epilogue writes packed ctx (pairs along d).
// =================================================================================
__global__ __launch_bounds__(128, 4) void fctx_mma(const float* __restrict__ relv)
{
    __shared__ float Sf[128][36];
    __shared__ uint32_t Ahp[128][PKP], Alp[128][PKP];
    __shared__ uint32_t Bhp[64][PKP2], Blp[64][PKP2];
    int z = blockIdx.y;
    int l0 = blockIdx.x * 128;
    int tid = threadIdx.x, warp = tid >> 5, lane = tid & 31;
    int warp_m = warp >> 1, warp_n = warp & 1;
    int g = lane >> 2, tg = lane & 3;
    int lq = lane & 7, ls1 = (lane >> 3) & 1, ls2 = lane >> 4;
    uint32_t uAh = (uint32_t)__cvta_generic_to_shared(Ahp);
    uint32_t uAl = (uint32_t)__cvta_generic_to_shared(Alp);
    const float* Vb = g_V + (size_t)z * Ss * DKk;
    float c[4][4][4] = {};

    int l = l0 + tid;
    float m = -INFINITY, Z = 0.f;
    {
        const float2* pp = &g_part[((size_t)z * Ss + l) * 8];
        float2 v[8];
        #pragma unroll
        for (int i = 0; i < 8; i++) { v[i] = pp[i]; m = fmaxf(m, v[i].x); }
        #pragma unroll
        for (int i = 0; i < 8; i++) Z += v[i].y * expf(v[i].x - m);
    }
    float invZ = 1.f / Z;
    float* arow = &g_arel[(size_t)(z * Ss + l) * Rr];
    for (int p = 1; p <= 127 - l; p++) arow[p] = 0.f;
    for (int p = 1152 - l; p <= 255; p++) arow[p] = 0.f;
    float p0a = 0.f, p256a = 0.f;

    for (int r0 = 0; r0 < Ss; r0 += KC) {
        for (int i = tid; i < 1024; i += 128) {
            int r = i >> 3, c4 = (i & 7) * 4;
            cpa16(&Sf[r][c4], &g_attn[(size_t)(z * Ss + l0 + r) * Ss + r0 + c4]);
        }
        for (int i = tid; i < 1024; i += 128) {
            int d = i & 63, pk = i >> 6;
            float v0 = Vb[(size_t)(r0 + 2 * pk) * DKk + d];
            float v1 = Vb[(size_t)(r0 + 2 * pk + 1) * DKk + d];
            split2(v0, v1, Bhp[d][pk], Blp[d][pk]);
        }
        CP_WAIT();
        __syncthreads();
        #pragma unroll
        for (int pc = 0; pc < PKC; pc++) {
            float s0 = Sf[tid][2 * pc], s1 = Sf[tid][2 * pc + 1];
            float p0f = expf(s0 - m) * invZ;
            float p1f = expf(s1 - m) * invZ;
            int rel0 = r0 + 2 * pc - l;
            if (rel0 <= -128) p0a += p0f;
            else if (rel0 >= 128) p256a += p0f;
            else arow[rel0 + 128] = p0f;
            int rel1 = rel0 + 1;
            if (rel1 <= -128) p0a += p1f;
            else if (rel1 >= 128) p256a += p1f;
            else arow[rel1 + 128] = p1f;
            split2(p0f, p1f, Ahp[tid][pc], Alp[tid][pc]);
        }
        __syncthreads();
        MMA_CHUNK_LDSM_A(Bhp, Blp)
        __syncthreads();
    }
    arow[0] = p0a;
    arow[256] = p256a;
    __syncthreads();

    for (int p0 = 0; p0 < Rr; p0 += KC) {
        for (int i = tid; i < 2048; i += 128) {
            int r = i >> 4, pc = i & 15;
            int p = p0 + 2 * pc;
            float a0 = (p     < Rr) ? g_arel[(size_t)(z * Ss + l0 + r) * Rr + p]     : 0.f;
            float a1 = (p + 1 < Rr) ? g_arel[(size_t)(z * Ss + l0 + r) * Rr + p + 1] : 0.f;
            split2(a0, a1, Ahp[r][pc], Alp[r][pc]);
        }
        for (int i = tid; i < 1024; i += 128) {
            int d = i & 63, pk = i >> 6;
            int p = p0 + 2 * pk;
            float v0 = (p     < Rr) ? relv[(size_t)p * DKk + d]       : 0.f;
            float v1 = (p + 1 < Rr) ? relv[(size_t)(p + 1) * DKk + d] : 0.f;
            split2(v0, v1, Bhp[d][pk], Blp[d][pk]);
        }
        __syncthreads();
        MMA_CHUNK_LDSM_A(Bhp, Blp)
        __syncthreads();
    }
    #pragma unroll
    for (int mt = 0; mt < 4; mt++)
        #pragma unroll
        for (int rr = 0; rr < 2; rr++) {
            int lr = l0 + warp_m * 64 + mt * 16 + g + rr * 8;
            #pragma unroll
            for (int nt = 0; nt < 4; nt++) {
                int d = warp_n * 32 + nt * 8 + tg * 2;
                uint32_t hh, ll;
                split2(c[mt][nt][rr * 2 + 0], c[mt][nt][rr * 2 + 1], hh, ll);
                size_t idx = ((size_t)z * Ss + lr) * 32 + (d >> 1);
                g_ch[idx] = hh; g_cl[idx] = ll;
            }
        }
}

// =================================================================================
// Kernel 5: outproj (packed ctx x packed w_o). grid (8, 32), 256 threads
// =================================================================================
__global__ __launch_bounds__(256, 2) void outproj_mma(const float* __restrict__ bo,
                                                      float* __restrict__ out)
{
    __shared__ uint32_t Ahp[128][PKP], Alp[128][PKP];
    __shared__ uint32_t Bhp[128][PKP], Blp[128][PKP];
    int n0 = blockIdx.x * 128, m0 = blockIdx.y * 128;
    int tid = threadIdx.x, warp = tid >> 5, lane = tid & 31;
    int warp_m = warp >> 2, warp_n = warp & 3;
    int lq = lane & 7, ls1 = (lane >> 3) & 1, ls2 = lane >> 4;
    uint32_t uAh = (uint32_t)__cvta_generic_to_shared(Ahp);
    uint32_t uAl = (uint32_t)__cvta_generic_to_shared(Alp);
    uint32_t uBh = (uint32_t)__cvta_generic_to_shared(Bhp);
    uint32_t uBl = (uint32_t)__cvta_generic_to_shared(Blp);
    uint32_t uBsel = (lane < 16) ? uBh : uBl;
    const uint32_t* Wh = g_wh + 3 * WP;
    const uint32_t* Wl = g_wl + 3 * WP;
    float c[4][4][4] = {};

    for (int k0 = 0; k0 < Dd; k0 += KC) {
        int h = k0 >> 6, pdk = (k0 & 63) >> 1, pk0 = k0 >> 1;
        for (int i = tid; i < 512; i += 256) {
            int r = i >> 2, p4 = (i & 3) << 2;
            int mm = m0 + r, b = mm >> 10, s = mm & 1023;
            size_t ai = ((size_t)(b * Hh + h) * Ss + s) * 32 + pdk + p4;
            cpa16(&Ahp[r][p4], &g_ch[ai]);
            cpa16(&Alp[r][p4], &g_cl[ai]);
            cpa16(&Bhp[r][p4], &Wh[(size_t)(n0 + r) * 512 + pk0 + p4]);
            cpa16(&Blp[r][p4], &Wl[(size_t)(n0 + r) * 512 + pk0 + p4]);
        }
        CP_WAIT();
        __syncthreads();
        MMA_CHUNK_LDSM()
        __syncthreads();
    }
    #pragma unroll
    for (int mt = 0; mt < 4; mt++)
        #pragma unroll
        for (int rr = 0; rr < 2; rr++) {
            int mm = m0 + warp_m * 64 + mt * 16 + (lane >> 2) + rr * 8;
            #pragma unroll
            for (int nt = 0; nt < 4; nt++) {
                int n = n0 + warp_n * 32 + nt * 8 + (lane & 3) * 2;
                out[(size_t)mm * Dd + n]     = c[mt][nt][rr * 2 + 0] + bo[n];
                out[(size_t)mm * Dd + n + 1] = c[mt][nt][rr * 2 + 1] + bo[n + 1];
            }
        }
}

extern "C" void kernel_launch(void* const* d_in, const int* in_sizes, int n_in,
                              void* d_out, int out_size)
{
    const float* query = (const float*)d_in[0];
    const float* key   = (const float*)d_in[1];
    const float* value = (const float*)d_in[2];
    const int*   mask  = (const int*)  d_in[3];
    const float* b_q   = (const float*)d_in[5];
    const float* b_k   = (const float*)d_in[7];
    const float* b_v   = (const float*)d_in[9];
    const float* b_o   = (const float*)d_in[11];
    const float* rel_k = (const float*)d_in[12];
    const float* rel_v = (const float*)d_in[13];
    const float* w_q   = (const float*)d_in[4];
    const float* w_k   = (const float*)d_in[6];
    const float* w_v   = (const float*)d_in[8];
    float* out = (float*)d_out;

    uint32_t *pInh, *pInl, *pWh, *pWl, *pRkh, *pRkl, *pQh, *pQl, *pKh, *pKl;
    float *pV;
    cudaGetSymbolAddress((void**)&pInh, g_inh);
    cudaGetSymbolAddress((void**)&pInl, g_inl);
    cudaGetSymbolAddress((void**)&pWh,  g_wh);
    cudaGetSymbolAddress((void**)&pWl,  g_wl);
    cudaGetSymbolAddress((void**)&pRkh, g_rkh);
    cudaGetSymbolAddress((void**)&pRkl, g_rkl);
    cudaGetSymbolAddress((void**)&pQh,  g_Qh);
    cudaGetSymbolAddress((void**)&pQl,  g_Ql);
    cudaGetSymbolAddress((void**)&pKh,  g_Kh);
    cudaGetSymbolAddress((void**)&pKl,  g_Kl);
    cudaGetSymbolAddress((void**)&pV,   g_V);

    // pre-split inputs, weights, rel_k (each element converted exactly once)
    presplit<<<INP / 256, 256>>>(query, pInh,           pInl,           INP);
    presplit<<<INP / 256, 256>>>(key,   pInh + INP,     pInl + INP,     INP);
    presplit<<<INP / 256, 256>>>(value, pInh + 2 * INP, pInl + 2 * INP, INP);
    presplit<<<WP / 256, 256>>>((const float*)d_in[4],  pWh,          pWl,          WP);
    presplit<<<WP / 256, 256>>>((const float*)d_in[6],  pWh + WP,     pWl + WP,     WP);
    presplit<<<WP / 256, 256>>>((const float*)d_in[8],  pWh + 2 * WP, pWl + 2 * WP, WP);
    presplit<<<WP / 256, 256>>>((const float*)d_in[10], pWh + 3 * WP, pWl + 3 * WP, WP);
    presplit<<<(8224 + 255) / 256, 256>>>(rel_k, pRkh, pRkl, 8224);
    (void)w_q; (void)w_k; (void)w_v;

    dim3 gProj(Dd / 128, Mm / 128);          // (8, 32)
    proj_mma<<<gProj, 256>>>(pInh,           pInl,           pWh,          pWl,          b_q, pQh, pQl, nullptr, 1);
    proj_mma<<<gProj, 256>>>(pInh + INP,     pInl + INP,     pWh + WP,     pWl + WP,     b_k, pKh, pKl, nullptr, 1);
    proj_mma<<<gProj, 256>>>(pInh + 2 * INP, pInl + 2 * INP, pWh + 2 * WP, pWl + 2 * WP, b_v, nullptr, nullptr, pV, 0);

    dim3 gQrel((Rr + 127) / 128, BHS / 128); // (3, 512)
    qrel_mma<<<gQrel, 256>>>();

    dim3 gScores(Ss / 128, Ss / 128, BHh);   // (8, 8, 64)
    scores_mma<<<gScores, 256>>>(mask);

    dim3 gCtx(Ss / 128, BHh);                // (8, 64)
    fctx_mma<<<gCtx, 128>>>(rel_v);

    dim3 gOut(Dd / 128, Mm / 128);           // (8, 32)
    outproj_mma<<<gOut, 256>>>(b_o, out);
}